// round 10
// baseline (speedup 1.0000x reference)
#include <cuda_runtime.h>
#include <cstdint>

// Problem shape (fixed by the dataset):
//   features:        (BS=4, C=64, P=12000) float32
//   x_orig_indices:  (BS, P) int32  (JAX x64 disabled: "int64" is silently int32)
//   y_orig_indices:  (BS, P) int32
//   output pseudo:   (BS, C, NY=440, NX=500) float32
#define BS     4
#define CCH    64
#define NP     12000
#define NXP    500
#define NYP    440
#define CELLS  (NXP * NYP)          // 220000
#define CELLS8 (CELLS / 8)          // 27500 cell8-groups per batch
#define NWORDS ((CELLS8 + 31) / 32) // 860 bitmap words per batch
#define NOUT   (BS * CCH * CELLS)   // 56,320,000

// Scratch (allocation-free device globals).
__device__ int            g_winner[BS * CELLS];   // (p+1) or 0; reset by pack
__device__ unsigned short g_w16[BS * CELLS];      // compressed winner
__device__ unsigned int   g_bitmap[BS * NWORDS];  // 1 bit per cell8 group

// ---------------------------------------------------------------------------
// Phase 1: winner pass — JAX sequential .set semantics == last p wins == max p.
// Also zeroes the bitmap for this launch (ordered before pack by kernel edge).
// ---------------------------------------------------------------------------
__global__ void winner_kernel(const int* __restrict__ xi,
                              const int* __restrict__ yi) {
    int i = blockIdx.x * blockDim.x + threadIdx.x;
    if (i < BS * NWORDS) g_bitmap[i] = 0u;
    if (i >= BS * NP) return;
    int b = i / NP;
    int p = i - b * NP;

    int x = xi[i];
    int y = yi[i];
    // jnp.clip semantics
    x = x < 0 ? 0 : (x >= NXP ? NXP - 1 : x);
    y = y < 0 ? 0 : (y >= NYP ? NYP - 1 : y);
    int cell = y * NXP + x;

    atomicMax(&g_winner[b * CELLS + cell], p + 1);
}

// ---------------------------------------------------------------------------
// Phase 2: pack int32 winner -> u16 + bitmap bit per cell8 group; reset the
// int32 winner for the next launch (sole reader -> replay-safe).
// ---------------------------------------------------------------------------
__global__ void pack_kernel() {
    const int n8 = BS * CELLS8;        // 110000
    int i = blockIdx.x * blockDim.x + threadIdx.x;
    if (i >= n8) return;
    int b     = i / CELLS8;
    int group = i - b * CELLS8;

    int4* wp = reinterpret_cast<int4*>(g_winner + b * CELLS) + group * 2;
    int4 w0 = wp[0];
    int4 w1 = wp[1];
    wp[0] = make_int4(0, 0, 0, 0);     // reset for next replay
    wp[1] = make_int4(0, 0, 0, 0);

    uint4 s;
    s.x = (unsigned int)(w0.x & 0xFFFF) | ((unsigned int)w0.y << 16);
    s.y = (unsigned int)(w0.z & 0xFFFF) | ((unsigned int)w0.w << 16);
    s.z = (unsigned int)(w1.x & 0xFFFF) | ((unsigned int)w1.y << 16);
    s.w = (unsigned int)(w1.z & 0xFFFF) | ((unsigned int)w1.w << 16);
    reinterpret_cast<uint4*>(g_w16 + b * CELLS)[group] = s;

    if (s.x | s.y | s.z | s.w)
        atomicOr(&g_bitmap[b * NWORDS + (group >> 5)], 1u << (group & 31));
}

// ---------------------------------------------------------------------------
// Phase 3: sparse overwrite. Runs AFTER the CE memset has zeroed the output.
// Only groups with >=1 winner store (full 16B vectors: zeros in non-winner
// lanes are identical to the memset -> sector-complete, no RMW, no race).
// ~73% of threads exit after one L1-broadcast bitmap word load.
// Store traffic ~60MB instead of 225MB; the 225MB zero-fill goes down the
// pure-write CE path concurrently with the winner/pack prologue.
// ---------------------------------------------------------------------------
__global__ void overwrite_kernel(const float* __restrict__ feat,
                                 float* __restrict__ out) {
    const int group = blockIdx.x * blockDim.x + threadIdx.x;  // cell8 in plane
    if (group >= CELLS8) return;
    const int bc = blockIdx.y;                                // b*CCH + c
    const int b  = bc >> 6;

    // One word covers 32 groups == exactly one warp -> broadcast load.
    unsigned int word = __ldg(&g_bitmap[b * NWORDS + (group >> 5)]);
    if (!((word >> (group & 31)) & 1u)) return;

    uint4 w = __ldg(reinterpret_cast<const uint4*>(g_w16 + b * CELLS) + group);
    const float* frow = feat + (size_t)bc * NP;   // 48KB row, L2-hot
    int p0 = (int)(w.x & 0xFFFFu), p1 = (int)(w.x >> 16);
    int p2 = (int)(w.y & 0xFFFFu), p3 = (int)(w.y >> 16);
    int p4 = (int)(w.z & 0xFFFFu), p5 = (int)(w.z >> 16);
    int p6 = (int)(w.w & 0xFFFFu), p7 = (int)(w.w >> 16);
    float4 v0, v1;
    v0.x = p0 ? __ldg(frow + p0 - 1) : 0.f;
    v0.y = p1 ? __ldg(frow + p1 - 1) : 0.f;
    v0.z = p2 ? __ldg(frow + p2 - 1) : 0.f;
    v0.w = p3 ? __ldg(frow + p3 - 1) : 0.f;
    v1.x = p4 ? __ldg(frow + p4 - 1) : 0.f;
    v1.y = p5 ? __ldg(frow + p5 - 1) : 0.f;
    v1.z = p6 ? __ldg(frow + p6 - 1) : 0.f;
    v1.w = p7 ? __ldg(frow + p7 - 1) : 0.f;

    float4* o = reinterpret_cast<float4*>(out + (size_t)bc * CELLS) + group * 2;
    o[0] = v0;
    o[1] = v1;
}

// ---------------------------------------------------------------------------
// Launch graph:
//   stream0: winner -> pack ----------------------\
//   s2:      [wait fork] memset(out, 225MB) ------+--> overwrite
// Fork/join via events (capture-legal: no sync, no alloc of device memory).
// Stream/event objects are created once (host-side CUDA objects, not device
// memory; the captured graph holds the dependency structure).
// ---------------------------------------------------------------------------
extern "C" void kernel_launch(void* const* d_in, const int* in_sizes, int n_in,
                              void* d_out, int out_size) {
    const float* feat = (const float*)d_in[0];
    const int*   xi   = (const int*)d_in[1];
    const int*   yi   = (const int*)d_in[2];
    float* out = (float*)d_out;

    static cudaStream_t s2 = nullptr;
    static cudaEvent_t  evFork = nullptr, evMemset = nullptr;
    if (s2 == nullptr) {
        cudaStreamCreateWithFlags(&s2, cudaStreamNonBlocking);
        cudaEventCreateWithFlags(&evFork,   cudaEventDisableTiming);
        cudaEventCreateWithFlags(&evMemset, cudaEventDisableTiming);
    }

    // Fork: zero-fill the 225MB output on the CE path, concurrent with the
    // winner/pack prologue on the compute stream.
    cudaEventRecord(evFork, 0);
    cudaStreamWaitEvent(s2, evFork, 0);
    cudaMemsetAsync(out, 0, (size_t)out_size * sizeof(float), s2);
    cudaEventRecord(evMemset, s2);

    {   // winner pass (+ bitmap zeroing)
        int n = BS * NP;
        int threads = 256;
        int blocks = (n + threads - 1) / threads;
        winner_kernel<<<blocks, threads>>>(xi, yi);
    }
    {   // pack to u16 + bitmap + reset
        int n = BS * CELLS8;
        int threads = 256;
        int blocks = (n + threads - 1) / threads;
        pack_kernel<<<blocks, threads>>>();
    }

    // Join: overwrite must see the zeroed output.
    cudaStreamWaitEvent(0, evMemset, 0);

    {   // sparse overwrite of winner-containing groups only
        dim3 grid((CELLS8 + 255) / 256, BS * CCH);   // (108, 256)
        overwrite_kernel<<<grid, 256>>>(feat, out);
    }
}

// round 11
// speedup vs baseline: 1.0280x; 1.0280x over previous
#include <cuda_runtime.h>
#include <cstdint>

// Problem shape (fixed by the dataset):
//   features:        (BS=4, C=64, P=12000) float32
//   x_orig_indices:  (BS, P) int32  (JAX x64 disabled: "int64" is silently int32)
//   y_orig_indices:  (BS, P) int32
//   output pseudo:   (BS, C, NY=440, NX=500) float32
#define BS     4
#define CCH    64
#define NP     12000
#define NXP    500
#define NYP    440
#define CELLS  (NXP * NYP)          // 220000
#define CELLS8 (CELLS / 8)          // 27500 cell8-groups per batch
#define NWORDS ((CELLS8 + 31) / 32) // 860 bitmap words per batch
#define NOUT   (BS * CCH * CELLS)   // 56,320,000

// Scratch (allocation-free device globals).
__device__ int            g_winner[BS * CELLS];   // (p+1) or 0; reset by pack
__device__ unsigned short g_w16[BS * CELLS];      // compressed winner
__device__ unsigned int   g_bitmap[BS * NWORDS];  // 1 bit per cell8 group

// ---------------------------------------------------------------------------
// Phase 1: winner pass — JAX sequential .set semantics == last p wins == max p.
// Also zeroes the bitmap for this launch (ordered before pack by kernel edge).
// ---------------------------------------------------------------------------
__global__ void winner_kernel(const int* __restrict__ xi,
                              const int* __restrict__ yi) {
    int i = blockIdx.x * blockDim.x + threadIdx.x;
    if (i < BS * NWORDS) g_bitmap[i] = 0u;
    if (i >= BS * NP) return;
    int b = i / NP;
    int p = i - b * NP;

    int x = xi[i];
    int y = yi[i];
    // jnp.clip semantics
    x = x < 0 ? 0 : (x >= NXP ? NXP - 1 : x);
    y = y < 0 ? 0 : (y >= NYP ? NYP - 1 : y);
    int cell = y * NXP + x;

    atomicMax(&g_winner[b * CELLS + cell], p + 1);
}

// ---------------------------------------------------------------------------
// Phase 2: pack int32 winner -> u16 + bitmap bit per cell8 group; reset the
// int32 winner for the next launch (sole reader -> replay-safe).
// ---------------------------------------------------------------------------
__global__ void pack_kernel() {
    const int n8 = BS * CELLS8;        // 110000
    int i = blockIdx.x * blockDim.x + threadIdx.x;
    if (i >= n8) return;
    int b     = i / CELLS8;
    int group = i - b * CELLS8;

    int4* wp = reinterpret_cast<int4*>(g_winner + b * CELLS) + group * 2;
    int4 w0 = wp[0];
    int4 w1 = wp[1];
    wp[0] = make_int4(0, 0, 0, 0);     // reset for next replay
    wp[1] = make_int4(0, 0, 0, 0);

    uint4 s;
    s.x = (unsigned int)(w0.x & 0xFFFF) | ((unsigned int)w0.y << 16);
    s.y = (unsigned int)(w0.z & 0xFFFF) | ((unsigned int)w0.w << 16);
    s.z = (unsigned int)(w1.x & 0xFFFF) | ((unsigned int)w1.y << 16);
    s.w = (unsigned int)(w1.z & 0xFFFF) | ((unsigned int)w1.w << 16);
    reinterpret_cast<uint4*>(g_w16 + b * CELLS)[group] = s;

    if (s.x | s.y | s.z | s.w)
        atomicOr(&g_bitmap[b * NWORDS + (group >> 5)], 1u << (group & 31));
}

// ---------------------------------------------------------------------------
// Phase 3: sparse overwrite. Runs AFTER the memset has zeroed the output.
// Only groups with >=1 winner store (full 16B vectors: zeros in non-winner
// lanes are identical to the memset -> sector-complete, no RMW, no race).
// ~65% of threads exit after one L1-broadcast bitmap word load.
// Store traffic ~80MB effective instead of the 225MB fused store stream.
// ---------------------------------------------------------------------------
__global__ void overwrite_kernel(const float* __restrict__ feat,
                                 float* __restrict__ out) {
    const int group = blockIdx.x * blockDim.x + threadIdx.x;  // cell8 in plane
    if (group >= CELLS8) return;
    const int bc = blockIdx.y;                                // b*CCH + c
    const int b  = bc >> 6;

    // One word covers 32 groups == exactly one warp -> broadcast load.
    unsigned int word = __ldg(&g_bitmap[b * NWORDS + (group >> 5)]);
    if (!((word >> (group & 31)) & 1u)) return;

    uint4 w = __ldg(reinterpret_cast<const uint4*>(g_w16 + b * CELLS) + group);
    const float* frow = feat + (size_t)bc * NP;   // 48KB row, L2-hot
    int p0 = (int)(w.x & 0xFFFFu), p1 = (int)(w.x >> 16);
    int p2 = (int)(w.y & 0xFFFFu), p3 = (int)(w.y >> 16);
    int p4 = (int)(w.z & 0xFFFFu), p5 = (int)(w.z >> 16);
    int p6 = (int)(w.w & 0xFFFFu), p7 = (int)(w.w >> 16);
    float4 v0, v1;
    v0.x = p0 ? __ldg(frow + p0 - 1) : 0.f;
    v0.y = p1 ? __ldg(frow + p1 - 1) : 0.f;
    v0.z = p2 ? __ldg(frow + p2 - 1) : 0.f;
    v0.w = p3 ? __ldg(frow + p3 - 1) : 0.f;
    v1.x = p4 ? __ldg(frow + p4 - 1) : 0.f;
    v1.y = p5 ? __ldg(frow + p5 - 1) : 0.f;
    v1.z = p6 ? __ldg(frow + p6 - 1) : 0.f;
    v1.w = p7 ? __ldg(frow + p7 - 1) : 0.f;

    float4* o = reinterpret_cast<float4*>(out + (size_t)bc * CELLS) + group * 2;
    o[0] = v0;
    o[1] = v1;
}

// ---------------------------------------------------------------------------
// Serial single-stream topology (R3 proved the serially-captured memset node
// runs ~35us; R10 proved the forked-stream variant runs ~60us — reverted).
//   memset(out) -> winner -> pack -> overwrite
// ---------------------------------------------------------------------------
extern "C" void kernel_launch(void* const* d_in, const int* in_sizes, int n_in,
                              void* d_out, int out_size) {
    const float* feat = (const float*)d_in[0];
    const int*   xi   = (const int*)d_in[1];
    const int*   yi   = (const int*)d_in[2];
    float* out = (float*)d_out;

    // Zero-fill the 225MB output (pure-write stream, fast path in-graph).
    cudaMemsetAsync(out, 0, (size_t)out_size * sizeof(float), 0);

    {   // winner pass (+ bitmap zeroing)
        int n = BS * NP;
        int threads = 256;
        int blocks = (n + threads - 1) / threads;
        winner_kernel<<<blocks, threads>>>(xi, yi);
    }
    {   // pack to u16 + bitmap + reset
        int n = BS * CELLS8;
        int threads = 256;
        int blocks = (n + threads - 1) / threads;
        pack_kernel<<<blocks, threads>>>();
    }
    {   // sparse overwrite of winner-containing groups only
        dim3 grid((CELLS8 + 255) / 256, BS * CCH);   // (108, 256)
        overwrite_kernel<<<grid, 256>>>(feat, out);
    }
}